// round 6
// baseline (speedup 1.0000x reference)
#include <cuda_runtime.h>
#include <cuda_fp16.h>
#include <cstdint>
#include <math_constants.h>

// Problem constants
#define DIM      256
#define NPIX     65536      // DIM*DIM
#define NOUT     16384      // HO*HO
#define HALF     32768      // pixels per half-plane
#define TPB      512
#define PAIRS    16         // output pairs per thread (32 outputs/thread)

// L2-resident compressed index table (4 x uint16 per output = 128 KB)
__device__ uint16_t g_idx16[NOUT * 4];

// ---------------------------------------------------------------------------
// Pass 0: compress gather_idx (int64 OR int32, autodetected) -> uint16.
// gather_idx is a permutation of [0,65536): among 8 sampled entries at most
// one is zero, so "first 8 odd u32 words all zero" <=> int64 layout.
// ---------------------------------------------------------------------------
__global__ void cvt_idx_kernel(const uint32_t* __restrict__ src) {
    bool is64 = true;
#pragma unroll
    for (int i = 0; i < 8; i++) is64 &= (src[2 * i + 1] == 0u);
    int t = blockIdx.x * blockDim.x + threadIdx.x;  // 0 .. 65535
    uint32_t v = is64 ? src[2 * t] : src[t];
    g_idx16[t] = (uint16_t)v;
}

// ---------------------------------------------------------------------------
// Main kernel: one CTA per plane, but only a 64 KB fp16 HALF-plane buffer so
// 3 CTAs co-reside per SM: one CTA's DRAM fill overlaps another's crossbar
// gather (fixes R5's phase serialization).
// Two passes per plane; candidates range-checked against the resident half.
// Cross-pass accumulators live in `out` (partial max written pass 0, read
// back pass 1 by the SAME thread -> no fence) to keep regs <= 42 for 3 CTAs.
// ---------------------------------------------------------------------------
extern __shared__ __half xh[];   // HALF halves = 64 KB dynamic

__global__ void __launch_bounds__(TPB, 3)
pool_kernel(const float* __restrict__ x, float* __restrict__ out) {
    const int plane = blockIdx.x;
    const int t = threadIdx.x;

    const float4* __restrict__ xp =
        reinterpret_cast<const float4*>(x + (size_t)plane * NPIX);
    uint2* __restrict__ sh = reinterpret_cast<uint2*>(xh);   // 4 halves each
    const uint4* __restrict__ idx4 =
        reinterpret_cast<const uint4*>(g_idx16);   // one uint4 = 2 outputs
    float* __restrict__ op = out + (size_t)plane * NOUT;

#pragma unroll
    for (int h = 0; h < 2; h++) {
        const unsigned base = h ? HALF : 0;

        // ---- fill this half: coalesced LDG.128 -> cvt -> STS.64 ----
#pragma unroll 4
        for (int w = 0; w < 16; w++) {
            const int q = t + w * TPB;               // 0 .. 8191 (float4)
            const float4 v = __ldcs(&xp[h * 8192 + q]);
            const __half2 h0 = __floats2half2_rn(v.x, v.y);
            const __half2 h1 = __floats2half2_rn(v.z, v.w);
            uint2 u;
            u.x = *reinterpret_cast<const unsigned*>(&h0);
            u.y = *reinterpret_cast<const unsigned*>(&h1);
            sh[q] = u;
        }
        __syncthreads();

        // ---- gather: 16 output-pairs/thread, predicated random LDS.16 ----
#pragma unroll 2
        for (int k = 0; k < PAIRS; k++) {
            const int p = t + k * TPB;               // pair index 0..8191
            const int o = 2 * p;
            const uint4 q = __ldg(&idx4[p]);
            float m0, m1;
            if (h) {                                  // resume partials
                const float2 prev = *reinterpret_cast<const float2*>(op + o);
                m0 = prev.x; m1 = prev.y;
            } else {
                m0 = -CUDART_INF_F; m1 = -CUDART_INF_F;
            }
            unsigned r;
            r = (q.x & 0xFFFFu) - base; if (r < HALF) m0 = fmaxf(m0, __half2float(xh[r]));
            r = (q.x >> 16)     - base; if (r < HALF) m0 = fmaxf(m0, __half2float(xh[r]));
            r = (q.y & 0xFFFFu) - base; if (r < HALF) m0 = fmaxf(m0, __half2float(xh[r]));
            r = (q.y >> 16)     - base; if (r < HALF) m0 = fmaxf(m0, __half2float(xh[r]));
            r = (q.z & 0xFFFFu) - base; if (r < HALF) m1 = fmaxf(m1, __half2float(xh[r]));
            r = (q.z >> 16)     - base; if (r < HALF) m1 = fmaxf(m1, __half2float(xh[r]));
            r = (q.w & 0xFFFFu) - base; if (r < HALF) m1 = fmaxf(m1, __half2float(xh[r]));
            r = (q.w >> 16)     - base; if (r < HALF) m1 = fmaxf(m1, __half2float(xh[r]));
            *reinterpret_cast<float2*>(op + o) = make_float2(m0, m1);
        }
        if (h == 0) __syncthreads();   // protect smem before refill
    }
}

// ---------------------------------------------------------------------------
// Launch
// ---------------------------------------------------------------------------
extern "C" void kernel_launch(void* const* d_in, const int* in_sizes, int n_in,
                              void* d_out, int out_size) {
    const float*    x    = (const float*)d_in[0];
    const uint32_t* gidx = (const uint32_t*)d_in[1];
    float*          out  = (float*)d_out;

    const int planes = in_sizes[0] / NPIX;            // 16*64 = 1024
    const int smem   = HALF * (int)sizeof(__half);    // 64 KB

    // Immediate (non-stream) API, idempotent -> capture-safe.
    cudaFuncSetAttribute(pool_kernel,
                         cudaFuncAttributeMaxDynamicSharedMemorySize, smem);

    cvt_idx_kernel<<<NPIX / 256, 256>>>(gidx);
    pool_kernel<<<planes, TPB, smem>>>(x, out);
}